// round 4
// baseline (speedup 1.0000x reference)
#include <cuda_runtime.h>
#include <cstdint>

// Problem constants
#define KDIM 1024
#define NHEAD 16
#define DHEAD 64
#define NB 2
#define NT 2048
#define MROWS (NB * NT)   // 4096

// Scratch (static device globals — no allocation allowed)
__device__ float g_Q[(size_t)MROWS * KDIM];     // [b,h,t,d]
__device__ float g_K[(size_t)MROWS * KDIM];     // [b,h,t,d]
__device__ float g_V[(size_t)MROWS * KDIM];     // [b,h,t,d]
__device__ float g_att[(size_t)MROWS * KDIM];   // [b*t, h*d]

// ---------------------------------------------------------------------------
// tf32 helpers
// ---------------------------------------------------------------------------
__device__ __forceinline__ uint32_t f2tf32(float x) {
    uint32_t r;
    asm("cvt.rna.tf32.f32 %0, %1;" : "=r"(r) : "f"(x));
    return r;
}

__device__ __forceinline__ void mma_tf32(float (&d)[4],
                                         const uint32_t (&a)[4],
                                         const uint32_t (&b)[2],
                                         const float (&c)[4]) {
    asm volatile(
        "mma.sync.aligned.m16n8k8.row.col.f32.tf32.tf32.f32 "
        "{%0,%1,%2,%3}, {%4,%5,%6,%7}, {%8,%9}, {%10,%11,%12,%13};\n"
        : "=f"(d[0]), "=f"(d[1]), "=f"(d[2]), "=f"(d[3])
        : "r"(a[0]), "r"(a[1]), "r"(a[2]), "r"(a[3]),
          "r"(b[0]), "r"(b[1]),
          "f"(c[0]), "f"(c[1]), "f"(c[2]), "f"(c[3]));
}

// ---------------------------------------------------------------------------
// tf32 mma GEMM: C[m,n] = sum_k A[m,k]*B[n,k].  Block tile 128x128x32.
// 256 threads = 8 warps in 2(M) x 4(N); warp tile 64x32 -> mma tiles 4x4.
// smem pitch 36 words (== 4 mod 32) -> conflict-free fragment LDS.
// ---------------------------------------------------------------------------
#define GBM 128
#define GBN 128
#define GBK 32
#define GPITCH 36

struct GemmFrag {
    float acc[4][4][4];
};

__device__ __forceinline__ void gemm_mma_core(
    const float* __restrict__ A, const float* __restrict__ B,
    uint32_t (*As)[GPITCH], uint32_t (*Bs)[GPITCH],
    float (&acc)[4][4][4], int m0, int n0)
{
    const int tid  = threadIdx.x;
    const int lane = tid & 31;
    const int w    = tid >> 5;
    const int wm   = w >> 2;       // 0..1
    const int wn   = w & 3;        // 0..3
    const int gid  = lane >> 2;    // 0..7
    const int ctid = lane & 3;     // 0..3

    const int lrow  = tid >> 3;        // 0..31
    const int lcol4 = (tid & 7) * 4;   // 0..28

    for (int k0 = 0; k0 < KDIM; k0 += GBK) {
#pragma unroll
        for (int i = 0; i < 4; i++) {
            int r = lrow + i * 32;
            float4 va = *(const float4*)(A + (size_t)(m0 + r) * KDIM + k0 + lcol4);
            uint4 ta = make_uint4(f2tf32(va.x), f2tf32(va.y), f2tf32(va.z), f2tf32(va.w));
            *(uint4*)&As[r][lcol4] = ta;
            float4 vb = *(const float4*)(B + (size_t)(n0 + r) * KDIM + k0 + lcol4);
            uint4 tb = make_uint4(f2tf32(vb.x), f2tf32(vb.y), f2tf32(vb.z), f2tf32(vb.w));
            *(uint4*)&Bs[r][lcol4] = tb;
        }
        __syncthreads();

#pragma unroll
        for (int kk = 0; kk < 4; kk++) {
            uint32_t a[4][4];
#pragma unroll
            for (int mt = 0; mt < 4; mt++) {
                int row = wm * 64 + mt * 16 + gid;
                int cb  = kk * 8 + ctid;
                a[mt][0] = As[row][cb];
                a[mt][1] = As[row + 8][cb];
                a[mt][2] = As[row][cb + 4];
                a[mt][3] = As[row + 8][cb + 4];
            }
            uint32_t b[4][2];
#pragma unroll
            for (int nt = 0; nt < 4; nt++) {
                int col = wn * 32 + nt * 8 + gid;
                int cb  = kk * 8 + ctid;
                b[nt][0] = Bs[col][cb];
                b[nt][1] = Bs[col][cb + 4];
            }
#pragma unroll
            for (int mt = 0; mt < 4; mt++)
#pragma unroll
                for (int nt = 0; nt < 4; nt++)
                    mma_tf32(acc[mt][nt], a[mt], b[nt], acc[mt][nt]);
        }
        __syncthreads();
    }
}

// QKV projection. WHICH: 0->g_Q 1->g_K 2->g_V; writes [b,h,t,d].
template<int WHICH>
__global__ __launch_bounds__(256, 2)
void qkv_gemm_kernel(const float* __restrict__ A, const float* __restrict__ W)
{
    __shared__ uint32_t As[GBM][GPITCH];
    __shared__ uint32_t Bs[GBN][GPITCH];
    float acc[4][4][4] = {};

    const int m0 = blockIdx.y * GBM;
    const int n0 = blockIdx.x * GBN;
    gemm_mma_core(A, W, As, Bs, acc, m0, n0);

    float* C = (WHICH == 0) ? g_Q : (WHICH == 1) ? g_K : g_V;
    const int lane = threadIdx.x & 31;
    const int w    = threadIdx.x >> 5;
    const int wm   = w >> 2, wn = w & 3;
    const int gid  = lane >> 2, ctid = lane & 3;

#pragma unroll
    for (int mt = 0; mt < 4; mt++) {
#pragma unroll
        for (int nt = 0; nt < 4; nt++) {
            int n    = n0 + wn * 32 + nt * 8 + 2 * ctid;
            int head = n >> 6;
            int dd   = n & 63;
#pragma unroll
            for (int rr = 0; rr < 2; rr++) {
                int m  = m0 + wm * 64 + mt * 16 + gid + rr * 8;
                int bb = m >> 11;
                int tt = m & 2047;
                float2 v = make_float2(acc[mt][nt][rr * 2], acc[mt][nt][rr * 2 + 1]);
                *(float2*)(C + ((size_t)((bb * NHEAD + head) * NT + tt)) * DHEAD + dd) = v;
            }
        }
    }
}

// Output projection: out = g_att @ Wo^T + bo.
__global__ __launch_bounds__(256, 2)
void out_gemm_kernel(const float* __restrict__ W, const float* __restrict__ bias,
                     float* __restrict__ out)
{
    __shared__ uint32_t As[GBM][GPITCH];
    __shared__ uint32_t Bs[GBN][GPITCH];
    float acc[4][4][4] = {};

    const int m0 = blockIdx.y * GBM;
    const int n0 = blockIdx.x * GBN;
    gemm_mma_core(g_att, W, As, Bs, acc, m0, n0);

    const int lane = threadIdx.x & 31;
    const int w    = threadIdx.x >> 5;
    const int wm   = w >> 2, wn = w & 3;
    const int gid  = lane >> 2, ctid = lane & 3;

#pragma unroll
    for (int mt = 0; mt < 4; mt++) {
#pragma unroll
        for (int nt = 0; nt < 4; nt++) {
            int n = n0 + wn * 32 + nt * 8 + 2 * ctid;
            float b0 = bias[n], b1 = bias[n + 1];
#pragma unroll
            for (int rr = 0; rr < 2; rr++) {
                int m = m0 + wm * 64 + mt * 16 + gid + rr * 8;
                float2 v = make_float2(acc[mt][nt][rr * 2] + b0,
                                       acc[mt][nt][rr * 2 + 1] + b1);
                *(float2*)(out + (size_t)m * KDIM + n) = v;
            }
        }
    }
}

// ---------------------------------------------------------------------------
// Flash attention with tf32 mma. Block = (b, h, 64 q-rows), 128 threads.
// Each warp owns 16 q-rows -> softmax reductions are warp-local (shfl).
// K-tile = 64. smem pitch 68 words -> conflict-free fragment LDS.
// ---------------------------------------------------------------------------
#define FPITCH 68
#define Q_OFF   0
#define K_OFF   (64 * FPITCH * 4)            // 17408
#define V_OFF   (2 * 64 * FPITCH * 4)        // 34816
#define P_OFF   (3 * 64 * FPITCH * 4)        // 52224
#define PAD_OFF (4 * 64 * FPITCH * 4)        // 69632
#define FA_SMEM (PAD_OFF + 64 * 4)           // 69888

__global__ __launch_bounds__(128, 3)
void flash_attn_kernel(const int* __restrict__ padding, float* __restrict__ out_att)
{
    extern __shared__ char smem_raw[];
    uint32_t (*Qs)[FPITCH] = (uint32_t(*)[FPITCH])(smem_raw + Q_OFF);
    uint32_t (*Ks)[FPITCH] = (uint32_t(*)[FPITCH])(smem_raw + K_OFF);
    uint32_t (*Vs)[FPITCH] = (uint32_t(*)[FPITCH])(smem_raw + V_OFF);
    uint32_t (*Ps)[FPITCH] = (uint32_t(*)[FPITCH])(smem_raw + P_OFF);
    float* padm = (float*)(smem_raw + PAD_OFF);

    const int tid  = threadIdx.x;
    const int lane = tid & 31;
    const int warp = tid >> 5;      // 0..3
    const int gid  = lane >> 2;     // 0..7
    const int ctid = lane & 3;      // 0..3

    const int q0 = blockIdx.x * 64;
    const int h  = blockIdx.y;
    const int bb = blockIdx.z;

    const float* Qbase = g_Q + ((size_t)(bb * NHEAD + h) * NT + q0) * DHEAD;
    const float* Kbase = g_K + (size_t)(bb * NHEAD + h) * NT * DHEAD;
    const float* Vbase = g_V + (size_t)(bb * NHEAD + h) * NT * DHEAD;
    const int*   pad   = padding + bb * NT;

    // Load Q tile 64x64 (cvt to tf32). 1024 float4 / 128 threads = 8 each.
#pragma unroll
    for (int i = 0; i < 8; i++) {
        int e = tid + i * 128;
        int r = e >> 4;
        int c = (e & 15) * 4;
        float4 v = *(const float4*)(Qbase + (size_t)r * DHEAD + c);
        uint4 t = make_uint4(f2tf32(v.x), f2tf32(v.y), f2tf32(v.z), f2tf32(v.w));
        *(uint4*)&Qs[r][c] = t;
    }

    float o[8][4];
#pragma unroll
    for (int j = 0; j < 8; j++)
#pragma unroll
        for (int c = 0; c < 4; c++) o[j][c] = 0.0f;
    float m0r = -1e30f, m1r = -1e30f;
    float l0r = 0.0f,   l1r = 0.0f;

    for (int kt = 0; kt < NT; kt += 64) {
        // Load K,V tiles and padding mask
#pragma unroll
        for (int i = 0; i < 8; i++) {
            int e = tid + i * 128;
            int r = e >> 4;
            int c = (e & 15) * 4;
            float4 vk = *(const float4*)(Kbase + (size_t)(kt + r) * DHEAD + c);
            *(uint4*)&Ks[r][c] = make_uint4(f2tf32(vk.x), f2tf32(vk.y), f2tf32(vk.z), f2tf32(vk.w));
            float4 vv = *(const float4*)(Vbase + (size_t)(kt + r) * DHEAD + c);
            *(uint4*)&Vs[r][c] = make_uint4(f2tf32(vv.x), f2tf32(vv.y), f2tf32(vv.z), f2tf32(vv.w));
        }
        if (tid < 64) padm[tid] = pad[kt + tid] ? 0.0f : -1e30f;
        __syncthreads();

        // S = Q K^T : warp's 16 q-rows x 64 k-cols, k-dim = d = 64.
        float s[8][4];
#pragma unroll
        for (int j = 0; j < 8; j++)
#pragma unroll
            for (int c = 0; c < 4; c++) s[j][c] = 0.0f;

#pragma unroll
        for (int kk = 0; kk < 8; kk++) {
            uint32_t aq[4];
            int row = warp * 16 + gid;
            int cb  = kk * 8 + ctid;
            aq[0] = Qs[row][cb];
            aq[1] = Qs[row + 8][cb];
            aq[2] = Qs[row][cb + 4];
            aq[3] = Qs[row + 8][cb + 4];
#pragma unroll
            for (int j = 0; j < 8; j++) {
                uint32_t bk[2];
                int col = j * 8 + gid;
                bk[0] = Ks[col][cb];
                bk[1] = Ks[col][cb + 4];
                mma_tf32(s[j], aq, bk, s[j]);
            }
        }

        // mask + scale; rows r0 = warp*16+gid (c0,c1), r1 = r0+8 (c2,c3)
        float mx0 = -1e30f, mx1 = -1e30f;
#pragma unroll
        for (int j = 0; j < 8; j++) {
            int col = j * 8 + 2 * ctid;
            float off0 = padm[col], off1 = padm[col + 1];
            s[j][0] = fmaf(s[j][0], 0.125f, off0);
            s[j][1] = fmaf(s[j][1], 0.125f, off1);
            s[j][2] = fmaf(s[j][2], 0.125f, off0);
            s[j][3] = fmaf(s[j][3], 0.125f, off1);
            mx0 = fmaxf(mx0, fmaxf(s[j][0], s[j][1]));
            mx1 = fmaxf(mx1, fmaxf(s[j][2], s[j][3]));
        }
        mx0 = fmaxf(mx0, __shfl_xor_sync(0xffffffffu, mx0, 1));
        mx0 = fmaxf(mx0, __shfl_xor_sync(0xffffffffu, mx0, 2));
        mx1 = fmaxf(mx1, __shfl_xor_sync(0xffffffffu, mx1, 1));
        mx1 = fmaxf(mx1, __shfl_xor_sync(0xffffffffu, mx1, 2));

        float mn0 = fmaxf(m0r, mx0);
        float mn1 = fmaxf(m1r, mx1);
        float corr0 = __expf(m0r - mn0);
        float corr1 = __expf(m1r - mn1);
        m0r = mn0; m1r = mn1;

        float rs0 = 0.0f, rs1 = 0.0f;
        int prow = warp * 16 + gid;
#pragma unroll
        for (int j = 0; j < 8; j++) {
            float p0 = __expf(s[j][0] - mn0);
            float p1 = __expf(s[j][1] - mn0);
            float p2 = __expf(s[j][2] - mn1);
            float p3 = __expf(s[j][3] - mn1);
            rs0 += p0 + p1;
            rs1 += p2 + p3;
            int col = j * 8 + 2 * ctid;
            Ps[prow][col]         = f2tf32(p0);
            Ps[prow][col + 1]     = f2tf32(p1);
            Ps[prow + 8][col]     = f2tf32(p2);
            Ps[prow + 8][col + 1] = f2tf32(p3);
        }
        rs0 += __shfl_xor_sync(0xffffffffu, rs0, 1);
        rs0 += __shfl_xor_sync(0xffffffffu, rs0, 2);
        rs1 += __shfl_xor_sync(0xffffffffu, rs1, 1);
        rs1 += __shfl_xor_sync(0xffffffffu, rs1, 2);
        l0r = l0r * corr0 + rs0;
        l1r = l1r * corr1 + rs1;

#pragma unroll
        for (int j = 0; j < 8; j++) {
            o[j][0] *= corr0; o[j][1] *= corr0;
            o[j][2] *= corr1; o[j][3] *= corr1;
        }
        __syncwarp();

        // O += P V : k-dim = 64 k-tokens, n = d = 64.
#pragma unroll
        for (int kk = 0; kk < 8; kk++) {
            uint32_t ap[4];
            int row = warp * 16 + gid;
            int cb  = kk * 8 + ctid;
            ap[0] = Ps[row][cb];
            ap[1] = Ps[row + 8][cb];
            ap[2] = Ps[row][cb + 4];
            ap[3] = Ps[row + 8][cb + 4];
#pragma unroll
            for (int j = 0; j < 8; j++) {
                uint32_t bv[2];
                int col = j * 8 + gid;
                bv[0] = Vs[kk * 8 + ctid][col];
                bv[1] = Vs[kk * 8 + ctid + 4][col];
                mma_tf32(o[j], ap, bv, o[j]);
            }
        }
        __syncthreads();
    }

    // Epilogue: normalize, write [b*t, h*d]
    float inv0 = 1.0f / l0r;
    float inv1 = 1.0f / l1r;
    int q = q0 + warp * 16 + gid;
#pragma unroll
    for (int j = 0; j < 8; j++) {
        int d = j * 8 + 2 * ctid;
        float* dst0 = out_att + ((size_t)(bb * NT + q)) * KDIM + h * DHEAD + d;
        float* dst1 = out_att + ((size_t)(bb * NT + q + 8)) * KDIM + h * DHEAD + d;
        *(float2*)dst0 = make_float2(o[j][0] * inv0, o[j][1] * inv0);
        *(float2*)dst1 = make_float2(o[j][2] * inv1, o[j][3] * inv1);
    }
}

// ---------------------------------------------------------------------------
// Launch
// ---------------------------------------------------------------------------
extern "C" void kernel_launch(void* const* d_in, const int* in_sizes, int n_in,
                              void* d_out, int out_size)
{
    const float* x       = (const float*)d_in[0];
    const int*   padding = (const int*)  d_in[1];
    const float* Wq      = (const float*)d_in[2];
    const float* Wk      = (const float*)d_in[3];
    const float* Wv      = (const float*)d_in[4];
    const float* Wo      = (const float*)d_in[5];
    const float* bo      = (const float*)d_in[6];
    float*       out     = (float*)d_out;

    static float* attp = nullptr;
    static bool init_done = false;
    if (!init_done) {
        cudaGetSymbolAddress((void**)&attp, g_att);
        cudaFuncSetAttribute(flash_attn_kernel,
                             cudaFuncAttributeMaxDynamicSharedMemorySize, FA_SMEM);
        init_done = true;
    }

    dim3 gemm_grid(KDIM / GBN, MROWS / GBM);   // (8, 32)
    qkv_gemm_kernel<0><<<gemm_grid, 256>>>(x, Wq);
    qkv_gemm_kernel<1><<<gemm_grid, 256>>>(x, Wk);
    qkv_gemm_kernel<2><<<gemm_grid, 256>>>(x, Wv);

    dim3 fa_grid(NT / 64, NHEAD, NB);          // (32, 16, 2)
    flash_attn_kernel<<<fa_grid, 128, FA_SMEM>>>(padding, attp);

    out_gemm_kernel<<<gemm_grid, 256>>>(Wo, bo, out);
}

// round 5
// speedup vs baseline: 1.0023x; 1.0023x over previous
#include <cuda_runtime.h>
#include <cstdint>

// Problem constants
#define KDIM 1024
#define NHEAD 16
#define DHEAD 64
#define NB 2
#define NT 2048
#define MROWS (NB * NT)   // 4096

// Scratch (static device globals — no allocation allowed)
__device__ float g_Q[(size_t)MROWS * KDIM];     // [b,h,t,d]
__device__ float g_K[(size_t)MROWS * KDIM];     // [b,h,t,d]
__device__ float g_V[(size_t)MROWS * KDIM];     // [b,h,t,d]
__device__ float g_att[(size_t)MROWS * KDIM];   // [b*t, h*d]

// ---------------------------------------------------------------------------
// tf32 helpers
// ---------------------------------------------------------------------------
__device__ __forceinline__ uint32_t f2tf32(float x) {
    uint32_t r;
    asm("cvt.rna.tf32.f32 %0, %1;" : "=r"(r) : "f"(x));
    return r;
}

__device__ __forceinline__ void mma_tf32(float (&d)[4],
                                         const uint32_t (&a)[4],
                                         const uint32_t (&b)[2],
                                         const float (&c)[4]) {
    asm volatile(
        "mma.sync.aligned.m16n8k8.row.col.f32.tf32.tf32.f32 "
        "{%0,%1,%2,%3}, {%4,%5,%6,%7}, {%8,%9}, {%10,%11,%12,%13};\n"
        : "=f"(d[0]), "=f"(d[1]), "=f"(d[2]), "=f"(d[3])
        : "r"(a[0]), "r"(a[1]), "r"(a[2]), "r"(a[3]),
          "r"(b[0]), "r"(b[1]),
          "f"(c[0]), "f"(c[1]), "f"(c[2]), "f"(c[3]));
}

// ---------------------------------------------------------------------------
// tf32 mma GEMM: C[m,n] = sum_k A[m,k]*B[n,k].  Block tile 128x128x32.
// 256 threads = 8 warps in 2(M) x 4(N); warp tile 64x32 -> mma tiles 4x4.
// smem pitch 36 words (== 4 mod 32) -> conflict-free fragment LDS.
// ---------------------------------------------------------------------------
#define GBM 128
#define GBN 128
#define GBK 32
#define GPITCH 36

struct GemmFrag {
    float acc[4][4][4];
};

__device__ __forceinline__ void gemm_mma_core(
    const float* __restrict__ A, const float* __restrict__ B,
    uint32_t (*As)[GPITCH], uint32_t (*Bs)[GPITCH],
    float (&acc)[4][4][4], int m0, int n0)
{
    const int tid  = threadIdx.x;
    const int lane = tid & 31;
    const int w    = tid >> 5;
    const int wm   = w >> 2;       // 0..1
    const int wn   = w & 3;        // 0..3
    const int gid  = lane >> 2;    // 0..7
    const int ctid = lane & 3;     // 0..3

    const int lrow  = tid >> 3;        // 0..31
    const int lcol4 = (tid & 7) * 4;   // 0..28

    for (int k0 = 0; k0 < KDIM; k0 += GBK) {
#pragma unroll
        for (int i = 0; i < 4; i++) {
            int r = lrow + i * 32;
            float4 va = *(const float4*)(A + (size_t)(m0 + r) * KDIM + k0 + lcol4);
            uint4 ta = make_uint4(f2tf32(va.x), f2tf32(va.y), f2tf32(va.z), f2tf32(va.w));
            *(uint4*)&As[r][lcol4] = ta;
            float4 vb = *(const float4*)(B + (size_t)(n0 + r) * KDIM + k0 + lcol4);
            uint4 tb = make_uint4(f2tf32(vb.x), f2tf32(vb.y), f2tf32(vb.z), f2tf32(vb.w));
            *(uint4*)&Bs[r][lcol4] = tb;
        }
        __syncthreads();

#pragma unroll
        for (int kk = 0; kk < 4; kk++) {
            uint32_t a[4][4];
#pragma unroll
            for (int mt = 0; mt < 4; mt++) {
                int row = wm * 64 + mt * 16 + gid;
                int cb  = kk * 8 + ctid;
                a[mt][0] = As[row][cb];
                a[mt][1] = As[row + 8][cb];
                a[mt][2] = As[row][cb + 4];
                a[mt][3] = As[row + 8][cb + 4];
            }
            uint32_t b[4][2];
#pragma unroll
            for (int nt = 0; nt < 4; nt++) {
                int col = wn * 32 + nt * 8 + gid;
                int cb  = kk * 8 + ctid;
                b[nt][0] = Bs[col][cb];
                b[nt][1] = Bs[col][cb + 4];
            }
#pragma unroll
            for (int mt = 0; mt < 4; mt++)
#pragma unroll
                for (int nt = 0; nt < 4; nt++)
                    mma_tf32(acc[mt][nt], a[mt], b[nt], acc[mt][nt]);
        }
        __syncthreads();
    }
}

// QKV projection. WHICH: 0->g_Q 1->g_K 2->g_V; writes [b,h,t,d].
template<int WHICH>
__global__ __launch_bounds__(256, 2)
void qkv_gemm_kernel(const float* __restrict__ A, const float* __restrict__ W)
{
    __shared__ uint32_t As[GBM][GPITCH];
    __shared__ uint32_t Bs[GBN][GPITCH];
    float acc[4][4][4] = {};

    const int m0 = blockIdx.y * GBM;
    const int n0 = blockIdx.x * GBN;
    gemm_mma_core(A, W, As, Bs, acc, m0, n0);

    float* C = (WHICH == 0) ? g_Q : (WHICH == 1) ? g_K : g_V;
    const int lane = threadIdx.x & 31;
    const int w    = threadIdx.x >> 5;
    const int wm   = w >> 2, wn = w & 3;
    const int gid  = lane >> 2, ctid = lane & 3;

#pragma unroll
    for (int mt = 0; mt < 4; mt++) {
#pragma unroll
        for (int nt = 0; nt < 4; nt++) {
            int n    = n0 + wn * 32 + nt * 8 + 2 * ctid;
            int head = n >> 6;
            int dd   = n & 63;
#pragma unroll
            for (int rr = 0; rr < 2; rr++) {
                int m  = m0 + wm * 64 + mt * 16 + gid + rr * 8;
                int bb = m >> 11;
                int tt = m & 2047;
                float2 v = make_float2(acc[mt][nt][rr * 2], acc[mt][nt][rr * 2 + 1]);
                *(float2*)(C + ((size_t)((bb * NHEAD + head) * NT + tt)) * DHEAD + dd) = v;
            }
        }
    }
}

// Output projection: out = g_att @ Wo^T + bo.
__global__ __launch_bounds__(256, 2)
void out_gemm_kernel(const float* __restrict__ W, const float* __restrict__ bias,
                     float* __restrict__ out)
{
    __shared__ uint32_t As[GBM][GPITCH];
    __shared__ uint32_t Bs[GBN][GPITCH];
    float acc[4][4][4] = {};

    const int m0 = blockIdx.y * GBM;
    const int n0 = blockIdx.x * GBN;
    gemm_mma_core(g_att, W, As, Bs, acc, m0, n0);

    const int lane = threadIdx.x & 31;
    const int w    = threadIdx.x >> 5;
    const int wm   = w >> 2, wn = w & 3;
    const int gid  = lane >> 2, ctid = lane & 3;

#pragma unroll
    for (int mt = 0; mt < 4; mt++) {
#pragma unroll
        for (int nt = 0; nt < 4; nt++) {
            int n = n0 + wn * 32 + nt * 8 + 2 * ctid;
            float b0 = bias[n], b1 = bias[n + 1];
#pragma unroll
            for (int rr = 0; rr < 2; rr++) {
                int m = m0 + wm * 64 + mt * 16 + gid + rr * 8;
                float2 v = make_float2(acc[mt][nt][rr * 2] + b0,
                                       acc[mt][nt][rr * 2 + 1] + b1);
                *(float2*)(out + (size_t)m * KDIM + n) = v;
            }
        }
    }
}

// ---------------------------------------------------------------------------
// Flash attention with tf32 mma. Block = (b, h, 64 q-rows), 128 threads.
// Each warp owns 16 q-rows -> softmax reductions are warp-local (shfl).
// K-tile = 64. smem pitch 68 words -> conflict-free fragment LDS.
// ---------------------------------------------------------------------------
#define FPITCH 68
#define Q_OFF   0
#define K_OFF   (64 * FPITCH * 4)            // 17408
#define V_OFF   (2 * 64 * FPITCH * 4)        // 34816
#define P_OFF   (3 * 64 * FPITCH * 4)        // 52224
#define PAD_OFF (4 * 64 * FPITCH * 4)        // 69632
#define FA_SMEM (PAD_OFF + 64 * 4)           // 69888

__global__ __launch_bounds__(128, 3)
void flash_attn_kernel(const int* __restrict__ padding, float* __restrict__ out_att)
{
    extern __shared__ char smem_raw[];
    uint32_t (*Qs)[FPITCH] = (uint32_t(*)[FPITCH])(smem_raw + Q_OFF);
    uint32_t (*Ks)[FPITCH] = (uint32_t(*)[FPITCH])(smem_raw + K_OFF);
    uint32_t (*Vs)[FPITCH] = (uint32_t(*)[FPITCH])(smem_raw + V_OFF);
    uint32_t (*Ps)[FPITCH] = (uint32_t(*)[FPITCH])(smem_raw + P_OFF);
    float* padm = (float*)(smem_raw + PAD_OFF);

    const int tid  = threadIdx.x;
    const int lane = tid & 31;
    const int warp = tid >> 5;      // 0..3
    const int gid  = lane >> 2;     // 0..7
    const int ctid = lane & 3;      // 0..3

    const int q0 = blockIdx.x * 64;
    const int h  = blockIdx.y;
    const int bb = blockIdx.z;

    const float* Qbase = g_Q + ((size_t)(bb * NHEAD + h) * NT + q0) * DHEAD;
    const float* Kbase = g_K + (size_t)(bb * NHEAD + h) * NT * DHEAD;
    const float* Vbase = g_V + (size_t)(bb * NHEAD + h) * NT * DHEAD;
    const int*   pad   = padding + bb * NT;

    // Load Q tile 64x64 (cvt to tf32). 1024 float4 / 128 threads = 8 each.
#pragma unroll
    for (int i = 0; i < 8; i++) {
        int e = tid + i * 128;
        int r = e >> 4;
        int c = (e & 15) * 4;
        float4 v = *(const float4*)(Qbase + (size_t)r * DHEAD + c);
        uint4 t = make_uint4(f2tf32(v.x), f2tf32(v.y), f2tf32(v.z), f2tf32(v.w));
        *(uint4*)&Qs[r][c] = t;
    }

    float o[8][4];
#pragma unroll
    for (int j = 0; j < 8; j++)
#pragma unroll
        for (int c = 0; c < 4; c++) o[j][c] = 0.0f;
    float m0r = -1e30f, m1r = -1e30f;
    float l0r = 0.0f,   l1r = 0.0f;

    for (int kt = 0; kt < NT; kt += 64) {
        // Load K,V tiles and padding mask
#pragma unroll
        for (int i = 0; i < 8; i++) {
            int e = tid + i * 128;
            int r = e >> 4;
            int c = (e & 15) * 4;
            float4 vk = *(const float4*)(Kbase + (size_t)(kt + r) * DHEAD + c);
            *(uint4*)&Ks[r][c] = make_uint4(f2tf32(vk.x), f2tf32(vk.y), f2tf32(vk.z), f2tf32(vk.w));
            float4 vv = *(const float4*)(Vbase + (size_t)(kt + r) * DHEAD + c);
            *(uint4*)&Vs[r][c] = make_uint4(f2tf32(vv.x), f2tf32(vv.y), f2tf32(vv.z), f2tf32(vv.w));
        }
        if (tid < 64) padm[tid] = pad[kt + tid] ? 0.0f : -1e30f;
        __syncthreads();

        // S = Q K^T : warp's 16 q-rows x 64 k-cols, k-dim = d = 64.
        float s[8][4];
#pragma unroll
        for (int j = 0; j < 8; j++)
#pragma unroll
            for (int c = 0; c < 4; c++) s[j][c] = 0.0f;

#pragma unroll
        for (int kk = 0; kk < 8; kk++) {
            uint32_t aq[4];
            int row = warp * 16 + gid;
            int cb  = kk * 8 + ctid;
            aq[0] = Qs[row][cb];
            aq[1] = Qs[row + 8][cb];
            aq[2] = Qs[row][cb + 4];
            aq[3] = Qs[row + 8][cb + 4];
#pragma unroll
            for (int j = 0; j < 8; j++) {
                uint32_t bk[2];
                int col = j * 8 + gid;
                bk[0] = Ks[col][cb];
                bk[1] = Ks[col][cb + 4];
                mma_tf32(s[j], aq, bk, s[j]);
            }
        }

        // mask + scale; rows r0 = warp*16+gid (c0,c1), r1 = r0+8 (c2,c3)
        float mx0 = -1e30f, mx1 = -1e30f;
#pragma unroll
        for (int j = 0; j < 8; j++) {
            int col = j * 8 + 2 * ctid;
            float off0 = padm[col], off1 = padm[col + 1];
            s[j][0] = fmaf(s[j][0], 0.125f, off0);
            s[j][1] = fmaf(s[j][1], 0.125f, off1);
            s[j][2] = fmaf(s[j][2], 0.125f, off0);
            s[j][3] = fmaf(s[j][3], 0.125f, off1);
            mx0 = fmaxf(mx0, fmaxf(s[j][0], s[j][1]));
            mx1 = fmaxf(mx1, fmaxf(s[j][2], s[j][3]));
        }
        mx0 = fmaxf(mx0, __shfl_xor_sync(0xffffffffu, mx0, 1));
        mx0 = fmaxf(mx0, __shfl_xor_sync(0xffffffffu, mx0, 2));
        mx1 = fmaxf(mx1, __shfl_xor_sync(0xffffffffu, mx1, 1));
        mx1 = fmaxf(mx1, __shfl_xor_sync(0xffffffffu, mx1, 2));

        float mn0 = fmaxf(m0r, mx0);
        float mn1 = fmaxf(m1r, mx1);
        float corr0 = __expf(m0r - mn0);
        float corr1 = __expf(m1r - mn1);
        m0r = mn0; m1r = mn1;

        float rs0 = 0.0f, rs1 = 0.0f;
        int prow = warp * 16 + gid;
#pragma unroll
        for (int j = 0; j < 8; j++) {
            float p0 = __expf(s[j][0] - mn0);
            float p1 = __expf(s[j][1] - mn0);
            float p2 = __expf(s[j][2] - mn1);
            float p3 = __expf(s[j][3] - mn1);
            rs0 += p0 + p1;
            rs1 += p2 + p3;
            int col = j * 8 + 2 * ctid;
            Ps[prow][col]         = f2tf32(p0);
            Ps[prow][col + 1]     = f2tf32(p1);
            Ps[prow + 8][col]     = f2tf32(p2);
            Ps[prow + 8][col + 1] = f2tf32(p3);
        }
        rs0 += __shfl_xor_sync(0xffffffffu, rs0, 1);
        rs0 += __shfl_xor_sync(0xffffffffu, rs0, 2);
        rs1 += __shfl_xor_sync(0xffffffffu, rs1, 1);
        rs1 += __shfl_xor_sync(0xffffffffu, rs1, 2);
        l0r = l0r * corr0 + rs0;
        l1r = l1r * corr1 + rs1;

#pragma unroll
        for (int j = 0; j < 8; j++) {
            o[j][0] *= corr0; o[j][1] *= corr0;
            o[j][2] *= corr1; o[j][3] *= corr1;
        }
        __syncwarp();

        // O += P V : k-dim = 64 k-tokens, n = d = 64.
#pragma unroll
        for (int kk = 0; kk < 8; kk++) {
            uint32_t ap[4];
            int row = warp * 16 + gid;
            int cb  = kk * 8 + ctid;
            ap[0] = Ps[row][cb];
            ap[1] = Ps[row + 8][cb];
            ap[2] = Ps[row][cb + 4];
            ap[3] = Ps[row + 8][cb + 4];
#pragma unroll
            for (int j = 0; j < 8; j++) {
                uint32_t bv[2];
                int col = j * 8 + gid;
                bv[0] = Vs[kk * 8 + ctid][col];
                bv[1] = Vs[kk * 8 + ctid + 4][col];
                mma_tf32(o[j], ap, bv, o[j]);
            }
        }
        __syncthreads();
    }

    // Epilogue: normalize, write [b*t, h*d]
    float inv0 = 1.0f / l0r;
    float inv1 = 1.0f / l1r;
    int q = q0 + warp * 16 + gid;
#pragma unroll
    for (int j = 0; j < 8; j++) {
        int d = j * 8 + 2 * ctid;
        float* dst0 = out_att + ((size_t)(bb * NT + q)) * KDIM + h * DHEAD + d;
        float* dst1 = out_att + ((size_t)(bb * NT + q + 8)) * KDIM + h * DHEAD + d;
        *(float2*)dst0 = make_float2(o[j][0] * inv0, o[j][1] * inv0);
        *(float2*)dst1 = make_float2(o[j][2] * inv1, o[j][3] * inv1);
    }
}

// ---------------------------------------------------------------------------
// Launch
// ---------------------------------------------------------------------------
extern "C" void kernel_launch(void* const* d_in, const int* in_sizes, int n_in,
                              void* d_out, int out_size)
{
    const float* x       = (const float*)d_in[0];
    const int*   padding = (const int*)  d_in[1];
    const float* Wq      = (const float*)d_in[2];
    const float* Wk      = (const float*)d_in[3];
    const float* Wv      = (const float*)d_in[4];
    const float* Wo      = (const float*)d_in[5];
    const float* bo      = (const float*)d_in[6];
    float*       out     = (float*)d_out;

    static float* attp = nullptr;
    static bool init_done = false;
    if (!init_done) {
        cudaGetSymbolAddress((void**)&attp, g_att);
        cudaFuncSetAttribute(flash_attn_kernel,
                             cudaFuncAttributeMaxDynamicSharedMemorySize, FA_SMEM);
        init_done = true;
    }

    dim3 gemm_grid(KDIM / GBN, MROWS / GBM);   // (8, 32)
    qkv_gemm_kernel<0><<<gemm_grid, 256>>>(x, Wq);
    qkv_gemm_kernel<1><<<gemm_grid, 256>>>(x, Wk);
    qkv_gemm_kernel<2><<<gemm_grid, 256>>>(x, Wv);

    dim3 fa_grid(NT / 64, NHEAD, NB);          // (32, 16, 2)
    flash_attn_kernel<<<fa_grid, 128, FA_SMEM>>>(padding, attp);

    out_gemm_kernel<<<gemm_grid, 256>>>(Wo, bo, out);
}

// round 6
// speedup vs baseline: 1.0039x; 1.0016x over previous
#include <cuda_runtime.h>
#include <cstdint>

// Problem constants
#define KDIM 1024
#define NHEAD 16
#define DHEAD 64
#define NB 2
#define NT 2048
#define MROWS (NB * NT)   // 4096

// Scratch (static device globals — no allocation allowed)
__device__ float g_Q[(size_t)MROWS * KDIM];     // [b,h,t,d]
__device__ float g_K[(size_t)MROWS * KDIM];     // [b,h,t,d]
__device__ float g_V[(size_t)MROWS * KDIM];     // [b,h,t,d]
__device__ float g_att[(size_t)MROWS * KDIM];   // [b*t, h*d]

// ---------------------------------------------------------------------------
// tf32 helpers
// ---------------------------------------------------------------------------
__device__ __forceinline__ uint32_t f2tf32(float x) {
    uint32_t r;
    asm("cvt.rna.tf32.f32 %0, %1;" : "=r"(r) : "f"(x));
    return r;
}

__device__ __forceinline__ void mma_tf32(float (&d)[4],
                                         const uint32_t (&a)[4],
                                         const uint32_t (&b)[2],
                                         const float (&c)[4]) {
    asm volatile(
        "mma.sync.aligned.m16n8k8.row.col.f32.tf32.tf32.f32 "
        "{%0,%1,%2,%3}, {%4,%5,%6,%7}, {%8,%9}, {%10,%11,%12,%13};\n"
        : "=f"(d[0]), "=f"(d[1]), "=f"(d[2]), "=f"(d[3])
        : "r"(a[0]), "r"(a[1]), "r"(a[2]), "r"(a[3]),
          "r"(b[0]), "r"(b[1]),
          "f"(c[0]), "f"(c[1]), "f"(c[2]), "f"(c[3]));
}

// ---------------------------------------------------------------------------
// tf32 mma GEMM: C[m,n] = sum_k A[m,k]*B[n,k].  Block tile 128x128x32.
// 256 threads = 8 warps in 2(M) x 4(N); warp tile 64x32 -> mma tiles 4x4.
// smem pitch 36 words (== 4 mod 32) -> conflict-free fragment LDS.
// ---------------------------------------------------------------------------
#define GBM 128
#define GBN 128
#define GBK 32
#define GPITCH 36

struct GemmFrag {
    float acc[4][4][4];
};

__device__ __forceinline__ void gemm_mma_core(
    const float* __restrict__ A, const float* __restrict__ B,
    uint32_t (*As)[GPITCH], uint32_t (*Bs)[GPITCH],
    float (&acc)[4][4][4], int m0, int n0)
{
    const int tid  = threadIdx.x;
    const int lane = tid & 31;
    const int w    = tid >> 5;
    const int wm   = w >> 2;       // 0..1
    const int wn   = w & 3;        // 0..3
    const int gid  = lane >> 2;    // 0..7
    const int ctid = lane & 3;     // 0..3

    const int lrow  = tid >> 3;        // 0..31
    const int lcol4 = (tid & 7) * 4;   // 0..28

    for (int k0 = 0; k0 < KDIM; k0 += GBK) {
#pragma unroll
        for (int i = 0; i < 4; i++) {
            int r = lrow + i * 32;
            float4 va = *(const float4*)(A + (size_t)(m0 + r) * KDIM + k0 + lcol4);
            uint4 ta = make_uint4(f2tf32(va.x), f2tf32(va.y), f2tf32(va.z), f2tf32(va.w));
            *(uint4*)&As[r][lcol4] = ta;
            float4 vb = *(const float4*)(B + (size_t)(n0 + r) * KDIM + k0 + lcol4);
            uint4 tb = make_uint4(f2tf32(vb.x), f2tf32(vb.y), f2tf32(vb.z), f2tf32(vb.w));
            *(uint4*)&Bs[r][lcol4] = tb;
        }
        __syncthreads();

#pragma unroll
        for (int kk = 0; kk < 4; kk++) {
            uint32_t a[4][4];
#pragma unroll
            for (int mt = 0; mt < 4; mt++) {
                int row = wm * 64 + mt * 16 + gid;
                int cb  = kk * 8 + ctid;
                a[mt][0] = As[row][cb];
                a[mt][1] = As[row + 8][cb];
                a[mt][2] = As[row][cb + 4];
                a[mt][3] = As[row + 8][cb + 4];
            }
            uint32_t b[4][2];
#pragma unroll
            for (int nt = 0; nt < 4; nt++) {
                int col = wn * 32 + nt * 8 + gid;
                int cb  = kk * 8 + ctid;
                b[nt][0] = Bs[col][cb];
                b[nt][1] = Bs[col][cb + 4];
            }
#pragma unroll
            for (int mt = 0; mt < 4; mt++)
#pragma unroll
                for (int nt = 0; nt < 4; nt++)
                    mma_tf32(acc[mt][nt], a[mt], b[nt], acc[mt][nt]);
        }
        __syncthreads();
    }
}

// QKV projection. WHICH: 0->g_Q 1->g_K 2->g_V; writes [b,h,t,d].
template<int WHICH>
__global__ __launch_bounds__(256, 2)
void qkv_gemm_kernel(const float* __restrict__ A, const float* __restrict__ W)
{
    __shared__ uint32_t As[GBM][GPITCH];
    __shared__ uint32_t Bs[GBN][GPITCH];
    float acc[4][4][4] = {};

    const int m0 = blockIdx.y * GBM;
    const int n0 = blockIdx.x * GBN;
    gemm_mma_core(A, W, As, Bs, acc, m0, n0);

    float* C = (WHICH == 0) ? g_Q : (WHICH == 1) ? g_K : g_V;
    const int lane = threadIdx.x & 31;
    const int w    = threadIdx.x >> 5;
    const int wm   = w >> 2, wn = w & 3;
    const int gid  = lane >> 2, ctid = lane & 3;

#pragma unroll
    for (int mt = 0; mt < 4; mt++) {
#pragma unroll
        for (int nt = 0; nt < 4; nt++) {
            int n    = n0 + wn * 32 + nt * 8 + 2 * ctid;
            int head = n >> 6;
            int dd   = n & 63;
#pragma unroll
            for (int rr = 0; rr < 2; rr++) {
                int m  = m0 + wm * 64 + mt * 16 + gid + rr * 8;
                int bb = m >> 11;
                int tt = m & 2047;
                float2 v = make_float2(acc[mt][nt][rr * 2], acc[mt][nt][rr * 2 + 1]);
                *(float2*)(C + ((size_t)((bb * NHEAD + head) * NT + tt)) * DHEAD + dd) = v;
            }
        }
    }
}

// Output projection: out = g_att @ Wo^T + bo.
__global__ __launch_bounds__(256, 2)
void out_gemm_kernel(const float* __restrict__ W, const float* __restrict__ bias,
                     float* __restrict__ out)
{
    __shared__ uint32_t As[GBM][GPITCH];
    __shared__ uint32_t Bs[GBN][GPITCH];
    float acc[4][4][4] = {};

    const int m0 = blockIdx.y * GBM;
    const int n0 = blockIdx.x * GBN;
    gemm_mma_core(g_att, W, As, Bs, acc, m0, n0);

    const int lane = threadIdx.x & 31;
    const int w    = threadIdx.x >> 5;
    const int wm   = w >> 2, wn = w & 3;
    const int gid  = lane >> 2, ctid = lane & 3;

#pragma unroll
    for (int mt = 0; mt < 4; mt++) {
#pragma unroll
        for (int nt = 0; nt < 4; nt++) {
            int n = n0 + wn * 32 + nt * 8 + 2 * ctid;
            float b0 = bias[n], b1 = bias[n + 1];
#pragma unroll
            for (int rr = 0; rr < 2; rr++) {
                int m = m0 + wm * 64 + mt * 16 + gid + rr * 8;
                float2 v = make_float2(acc[mt][nt][rr * 2] + b0,
                                       acc[mt][nt][rr * 2 + 1] + b1);
                *(float2*)(out + (size_t)m * KDIM + n) = v;
            }
        }
    }
}

// ---------------------------------------------------------------------------
// Flash attention with tf32 mma. Block = (b, h, 64 q-rows), 128 threads.
// Each warp owns 16 q-rows -> softmax reductions are warp-local (shfl).
// K-tile = 64. smem pitch 68 words -> conflict-free fragment LDS.
// ---------------------------------------------------------------------------
#define FPITCH 68
#define Q_OFF   0
#define K_OFF   (64 * FPITCH * 4)            // 17408
#define V_OFF   (2 * 64 * FPITCH * 4)        // 34816
#define P_OFF   (3 * 64 * FPITCH * 4)        // 52224
#define PAD_OFF (4 * 64 * FPITCH * 4)        // 69632
#define FA_SMEM (PAD_OFF + 64 * 4)           // 69888

__global__ __launch_bounds__(128, 3)
void flash_attn_kernel(const int* __restrict__ padding, float* __restrict__ out_att)
{
    extern __shared__ char smem_raw[];
    uint32_t (*Qs)[FPITCH] = (uint32_t(*)[FPITCH])(smem_raw + Q_OFF);
    uint32_t (*Ks)[FPITCH] = (uint32_t(*)[FPITCH])(smem_raw + K_OFF);
    uint32_t (*Vs)[FPITCH] = (uint32_t(*)[FPITCH])(smem_raw + V_OFF);
    uint32_t (*Ps)[FPITCH] = (uint32_t(*)[FPITCH])(smem_raw + P_OFF);
    float* padm = (float*)(smem_raw + PAD_OFF);

    const int tid  = threadIdx.x;
    const int lane = tid & 31;
    const int warp = tid >> 5;      // 0..3
    const int gid  = lane >> 2;     // 0..7
    const int ctid = lane & 3;      // 0..3

    const int q0 = blockIdx.x * 64;
    const int h  = blockIdx.y;
    const int bb = blockIdx.z;

    const float* Qbase = g_Q + ((size_t)(bb * NHEAD + h) * NT + q0) * DHEAD;
    const float* Kbase = g_K + (size_t)(bb * NHEAD + h) * NT * DHEAD;
    const float* Vbase = g_V + (size_t)(bb * NHEAD + h) * NT * DHEAD;
    const int*   pad   = padding + bb * NT;

    // Load Q tile 64x64 (cvt to tf32). 1024 float4 / 128 threads = 8 each.
#pragma unroll
    for (int i = 0; i < 8; i++) {
        int e = tid + i * 128;
        int r = e >> 4;
        int c = (e & 15) * 4;
        float4 v = *(const float4*)(Qbase + (size_t)r * DHEAD + c);
        uint4 t = make_uint4(f2tf32(v.x), f2tf32(v.y), f2tf32(v.z), f2tf32(v.w));
        *(uint4*)&Qs[r][c] = t;
    }

    float o[8][4];
#pragma unroll
    for (int j = 0; j < 8; j++)
#pragma unroll
        for (int c = 0; c < 4; c++) o[j][c] = 0.0f;
    float m0r = -1e30f, m1r = -1e30f;
    float l0r = 0.0f,   l1r = 0.0f;

    for (int kt = 0; kt < NT; kt += 64) {
        // Load K,V tiles and padding mask
#pragma unroll
        for (int i = 0; i < 8; i++) {
            int e = tid + i * 128;
            int r = e >> 4;
            int c = (e & 15) * 4;
            float4 vk = *(const float4*)(Kbase + (size_t)(kt + r) * DHEAD + c);
            *(uint4*)&Ks[r][c] = make_uint4(f2tf32(vk.x), f2tf32(vk.y), f2tf32(vk.z), f2tf32(vk.w));
            float4 vv = *(const float4*)(Vbase + (size_t)(kt + r) * DHEAD + c);
            *(uint4*)&Vs[r][c] = make_uint4(f2tf32(vv.x), f2tf32(vv.y), f2tf32(vv.z), f2tf32(vv.w));
        }
        if (tid < 64) padm[tid] = pad[kt + tid] ? 0.0f : -1e30f;
        __syncthreads();

        // S = Q K^T : warp's 16 q-rows x 64 k-cols, k-dim = d = 64.
        float s[8][4];
#pragma unroll
        for (int j = 0; j < 8; j++)
#pragma unroll
            for (int c = 0; c < 4; c++) s[j][c] = 0.0f;

#pragma unroll
        for (int kk = 0; kk < 8; kk++) {
            uint32_t aq[4];
            int row = warp * 16 + gid;
            int cb  = kk * 8 + ctid;
            aq[0] = Qs[row][cb];
            aq[1] = Qs[row + 8][cb];
            aq[2] = Qs[row][cb + 4];
            aq[3] = Qs[row + 8][cb + 4];
#pragma unroll
            for (int j = 0; j < 8; j++) {
                uint32_t bk[2];
                int col = j * 8 + gid;
                bk[0] = Ks[col][cb];
                bk[1] = Ks[col][cb + 4];
                mma_tf32(s[j], aq, bk, s[j]);
            }
        }

        // mask + scale; rows r0 = warp*16+gid (c0,c1), r1 = r0+8 (c2,c3)
        float mx0 = -1e30f, mx1 = -1e30f;
#pragma unroll
        for (int j = 0; j < 8; j++) {
            int col = j * 8 + 2 * ctid;
            float off0 = padm[col], off1 = padm[col + 1];
            s[j][0] = fmaf(s[j][0], 0.125f, off0);
            s[j][1] = fmaf(s[j][1], 0.125f, off1);
            s[j][2] = fmaf(s[j][2], 0.125f, off0);
            s[j][3] = fmaf(s[j][3], 0.125f, off1);
            mx0 = fmaxf(mx0, fmaxf(s[j][0], s[j][1]));
            mx1 = fmaxf(mx1, fmaxf(s[j][2], s[j][3]));
        }
        mx0 = fmaxf(mx0, __shfl_xor_sync(0xffffffffu, mx0, 1));
        mx0 = fmaxf(mx0, __shfl_xor_sync(0xffffffffu, mx0, 2));
        mx1 = fmaxf(mx1, __shfl_xor_sync(0xffffffffu, mx1, 1));
        mx1 = fmaxf(mx1, __shfl_xor_sync(0xffffffffu, mx1, 2));

        float mn0 = fmaxf(m0r, mx0);
        float mn1 = fmaxf(m1r, mx1);
        float corr0 = __expf(m0r - mn0);
        float corr1 = __expf(m1r - mn1);
        m0r = mn0; m1r = mn1;

        float rs0 = 0.0f, rs1 = 0.0f;
        int prow = warp * 16 + gid;
#pragma unroll
        for (int j = 0; j < 8; j++) {
            float p0 = __expf(s[j][0] - mn0);
            float p1 = __expf(s[j][1] - mn0);
            float p2 = __expf(s[j][2] - mn1);
            float p3 = __expf(s[j][3] - mn1);
            rs0 += p0 + p1;
            rs1 += p2 + p3;
            int col = j * 8 + 2 * ctid;
            Ps[prow][col]         = f2tf32(p0);
            Ps[prow][col + 1]     = f2tf32(p1);
            Ps[prow + 8][col]     = f2tf32(p2);
            Ps[prow + 8][col + 1] = f2tf32(p3);
        }
        rs0 += __shfl_xor_sync(0xffffffffu, rs0, 1);
        rs0 += __shfl_xor_sync(0xffffffffu, rs0, 2);
        rs1 += __shfl_xor_sync(0xffffffffu, rs1, 1);
        rs1 += __shfl_xor_sync(0xffffffffu, rs1, 2);
        l0r = l0r * corr0 + rs0;
        l1r = l1r * corr1 + rs1;

#pragma unroll
        for (int j = 0; j < 8; j++) {
            o[j][0] *= corr0; o[j][1] *= corr0;
            o[j][2] *= corr1; o[j][3] *= corr1;
        }
        __syncwarp();

        // O += P V : k-dim = 64 k-tokens, n = d = 64.
#pragma unroll
        for (int kk = 0; kk < 8; kk++) {
            uint32_t ap[4];
            int row = warp * 16 + gid;
            int cb  = kk * 8 + ctid;
            ap[0] = Ps[row][cb];
            ap[1] = Ps[row + 8][cb];
            ap[2] = Ps[row][cb + 4];
            ap[3] = Ps[row + 8][cb + 4];
#pragma unroll
            for (int j = 0; j < 8; j++) {
                uint32_t bv[2];
                int col = j * 8 + gid;
                bv[0] = Vs[kk * 8 + ctid][col];
                bv[1] = Vs[kk * 8 + ctid + 4][col];
                mma_tf32(o[j], ap, bv, o[j]);
            }
        }
        __syncthreads();
    }

    // Epilogue: normalize, write [b*t, h*d]
    float inv0 = 1.0f / l0r;
    float inv1 = 1.0f / l1r;
    int q = q0 + warp * 16 + gid;
#pragma unroll
    for (int j = 0; j < 8; j++) {
        int d = j * 8 + 2 * ctid;
        float* dst0 = out_att + ((size_t)(bb * NT + q)) * KDIM + h * DHEAD + d;
        float* dst1 = out_att + ((size_t)(bb * NT + q + 8)) * KDIM + h * DHEAD + d;
        *(float2*)dst0 = make_float2(o[j][0] * inv0, o[j][1] * inv0);
        *(float2*)dst1 = make_float2(o[j][2] * inv1, o[j][3] * inv1);
    }
}

// ---------------------------------------------------------------------------
// Launch
// ---------------------------------------------------------------------------
extern "C" void kernel_launch(void* const* d_in, const int* in_sizes, int n_in,
                              void* d_out, int out_size)
{
    const float* x       = (const float*)d_in[0];
    const int*   padding = (const int*)  d_in[1];
    const float* Wq      = (const float*)d_in[2];
    const float* Wk      = (const float*)d_in[3];
    const float* Wv      = (const float*)d_in[4];
    const float* Wo      = (const float*)d_in[5];
    const float* bo      = (const float*)d_in[6];
    float*       out     = (float*)d_out;

    static float* attp = nullptr;
    static bool init_done = false;
    if (!init_done) {
        cudaGetSymbolAddress((void**)&attp, g_att);
        cudaFuncSetAttribute(flash_attn_kernel,
                             cudaFuncAttributeMaxDynamicSharedMemorySize, FA_SMEM);
        init_done = true;
    }

    dim3 gemm_grid(KDIM / GBN, MROWS / GBM);   // (8, 32)
    qkv_gemm_kernel<0><<<gemm_grid, 256>>>(x, Wq);
    qkv_gemm_kernel<1><<<gemm_grid, 256>>>(x, Wk);
    qkv_gemm_kernel<2><<<gemm_grid, 256>>>(x, Wv);

    dim3 fa_grid(NT / 64, NHEAD, NB);          // (32, 16, 2)
    flash_attn_kernel<<<fa_grid, 128, FA_SMEM>>>(padding, attp);

    out_gemm_kernel<<<gemm_grid, 256>>>(Wo, bo, out);
}